// round 1
// baseline (speedup 1.0000x reference)
#include <cuda_runtime.h>
#include <cstdint>

// Problem constants (fixed by the reference)
#define L_SEQ 1024
#define N_ST  256

// Output layout: concat of (c_all[L,N], y_all[L], GBT_A[L,N,N], GBT_B[L,N])
#define OFF_C  ((size_t)0)
#define OFF_Y  ((size_t)(L_SEQ * N_ST))                       // 262144
#define OFF_A  (OFF_Y + (size_t)L_SEQ)                        // 263168
#define OFF_B  (OFF_A + (size_t)L_SEQ * N_ST * N_ST)          // 67372032

// Fast reciprocal: rcp.approx + 1 Newton step (effectively correctly rounded)
__device__ __forceinline__ float frcp(float x) {
    float t;
    asm("rcp.approx.f32 %0, %1;" : "=f"(t) : "f"(x));
    t = fmaf(t, fmaf(-x, t, 1.0f), t);
    return t;
}

// ---------------------------------------------------------------------------
// Kernel A: GBT_A[k] = 2*P1^{-1} - I  for step size ss = 1/(k+1), s = ss/2.
// P1 is lower triangular: diag e_i = 1 + s*(i+1), strict lower = s*r_i*r_j.
// Column j of M = P1^{-1} via forward substitution:
//   x_j = 1/e_j ; for i>j: x_i = -a_i*S, S += r_i*x_i   (a_i = s*r_i/e_i)
// Thread j owns column j; all 256 threads store row i together (coalesced).
// ---------------------------------------------------------------------------
__global__ void __launch_bounds__(N_ST) hippo_fillA(
        const float* __restrict__ Bvec, float* __restrict__ out) {
    __shared__ float r_s[N_ST];
    __shared__ float a_s[N_ST];

    const int k = blockIdx.x;
    const int j = threadIdx.x;

    const float ss = 1.0f / (float)(k + 1);
    const float s  = 0.5f * ss;

    const float rj     = Bvec[j];                       // r_j = sqrt(2j+1)
    const float ej     = fmaf(s, (float)(j + 1), 1.0f); // e_j
    const float inv_ej = 1.0f / ej;

    r_s[j] = rj;
    a_s[j] = s * rj * inv_ej;
    __syncthreads();

    float* outA = out + OFF_A + (size_t)k * (N_ST * N_ST) + j;

    float x = 0.0f, S = 0.0f;
    #pragma unroll 4
    for (int i = 0; i < N_ST; i++) {
        float val;
        if (i < j) {
            val = 0.0f;                                  // Ad strictly upper = 0
        } else if (i == j) {
            x = inv_ej;                                  // M_jj
            S = rj * x;
            val = fmaf(2.0f, x, -1.0f);                  // diag of 2M - I
        } else {
            x = -a_s[i] * S;                             // M_ij
            S = fmaf(r_s[i], x, S);
            val = 2.0f * x;
        }
        outA[(size_t)i * N_ST] = val;
    }
}

// ---------------------------------------------------------------------------
// Kernel B: systolic scan over time.
//   c_k = Ad_k c_{k-1} + Bd_k f_k = 2*z - c_{k-1} + Bd*f_k, where P1 z = c_{k-1}
//   Solve recurrences (share coefficients):
//     z_i  = inv_e*(c_i - s*r_i*V),  V += r_i*z_i
//     yb_i = inv_e*(r_i - s*r_i*S),  S += r_i*yb_i,  Bd_i = ss*yb_i
// One warp; lane l owns states i in [8l, 8l+8). At tick tau, lane l processes
// time step k = tau - l, receiving (V,S,ysum) from lane l-1 via shfl.up
// (those are lane l-1's end-of-step-k values from the previous tick).
// Writes c_all, y_all, GBT_B.
// ---------------------------------------------------------------------------
__global__ void __launch_bounds__(32) hippo_scan(
        const float* __restrict__ f,
        const float* __restrict__ initS,
        const float* __restrict__ Bvec,
        float* __restrict__ out) {
    __shared__ float fbuf[L_SEQ];
    const int lane = threadIdx.x;

    // Stage f into shared (single warp -> syncwarp suffices)
    for (int idx = lane; idx < L_SEQ; idx += 32) fbuf[idx] = f[idx];
    __syncwarp();

    const int ib = lane * 8;
    float r[8], c[8];
    #pragma unroll
    for (int e = 0; e < 8; e++) {
        r[e] = Bvec[ib + e];
        c[e] = initS[ib + e];
    }

    float* outC = out + OFF_C;
    float* outY = out + OFF_Y;
    float* outB = out + OFF_B;

    float V = 0.0f, S = 0.0f, ys = 0.0f;

    for (int tau = 0; tau < L_SEQ + 31; tau++) {
        // Receive left neighbor's end-of-previous-tick state (same time step k)
        float Vin = __shfl_up_sync(0xffffffffu, V, 1);
        float Sin = __shfl_up_sync(0xffffffffu, S, 1);
        float yin = __shfl_up_sync(0xffffffffu, ys, 1);
        if (lane == 0) { Vin = 0.0f; Sin = 0.0f; yin = 0.0f; }

        const int k = tau - lane;
        if (k >= 0 && k < L_SEQ) {
            const float ss = frcp((float)(k + 1));
            const float s  = 0.5f * ss;
            const float fk = fbuf[k];

            V = Vin; S = Sin; ys = yin;

            float cb[8], bb[8];
            #pragma unroll
            for (int e = 0; e < 8; e++) {
                const int   i  = ib + e;
                const float ef = fmaf(s, (float)(i + 1), 1.0f);  // e_i
                const float ie = frcp(ef);                        // 1/e_i
                const float sr = s * r[e];

                float z = ie * fmaf(-sr, V, c[e]);   // z_i = Mc_i
                V = fmaf(r[e], z, V);

                float yb = ie * fmaf(-sr, S, r[e]);  // Bd solve
                S = fmaf(r[e], yb, S);
                float Bd = ss * yb;

                float cn = fmaf(2.0f, z, fmaf(Bd, fk, -c[e]));
                ys += cn;
                c[e] = cn;
                cb[e] = cn;
                bb[e] = Bd;
            }

            // Coalesced-ish 16B stores: 8 consecutive floats per lane
            float4* pc = (float4*)(outC + (size_t)k * N_ST + ib);
            pc[0] = make_float4(cb[0], cb[1], cb[2], cb[3]);
            pc[1] = make_float4(cb[4], cb[5], cb[6], cb[7]);
            float4* pb = (float4*)(outB + (size_t)k * N_ST + ib);
            pb[0] = make_float4(bb[0], bb[1], bb[2], bb[3]);
            pb[1] = make_float4(bb[4], bb[5], bb[6], bb[7]);

            if (lane == 31) outY[k] = ys;            // y_k = sum_i c_i
        } else {
            // Invalid step: emit zeros; consumer only reads these when its own
            // k is also out of range, so values are never used meaningfully.
            V = 0.0f; S = 0.0f; ys = 0.0f;
        }
    }
}

// ---------------------------------------------------------------------------
extern "C" void kernel_launch(void* const* d_in, const int* in_sizes, int n_in,
                              void* d_out, int out_size) {
    const float* f    = (const float*)d_in[0];  // (L,1)
    const float* init = (const float*)d_in[1];  // (N,1)
    // d_in[2] = A (unused: closed form), d_in[3] = B (= r vector)
    const float* B    = (const float*)d_in[3];
    float* out = (float*)d_out;

    hippo_fillA<<<L_SEQ, N_ST>>>(B, out);
    hippo_scan<<<1, 32>>>(f, init, B, out);
}